// round 10
// baseline (speedup 1.0000x reference)
#include <cuda_runtime.h>
#include <cuda_bf16.h>
#include <math.h>
#include <stdint.h>

#define BB  4
#define TT  2048
#define DD  128
#define VV  64
#define LL  12
#define HMM 512
#define BTT (BB*TT)   // 8192

// ---------------- scratch ----------------
__device__ float          g_H  [BTT*DD];
__device__ __nv_bfloat16  g_H1b[BTT*DD];
__device__ __nv_bfloat16  g_Qb [BTT*DD];
__device__ __nv_bfloat16  g_Kb [BTT*DD];
__device__ __nv_bfloat16  g_Vb [BTT*DD];
__device__ __nv_bfloat16  g_M1b[BTT*HMM];
__device__ __nv_bfloat16  g_Wqkvb[LL*3*DD*DD];
__device__ __nv_bfloat16  g_W1b[LL*HMM*DD];
__device__ __nv_bfloat16  g_W2b[LL*DD*HMM];

// ---------------- helpers ----------------
__device__ __forceinline__ uint32_t smem_u32(const void* p) {
    uint32_t a;
    asm("{ .reg .u64 t; cvta.to.shared.u64 t, %1; cvt.u32.u64 %0, t; }" : "=r"(a) : "l"(p));
    return a;
}
__device__ __forceinline__ void cp16(uint32_t saddr, const void* gaddr) {
    asm volatile("cp.async.cg.shared.global [%0], [%1], 16;" :: "r"(saddr), "l"(gaddr) : "memory");
}
__device__ __forceinline__ void cp_commit() { asm volatile("cp.async.commit_group;" ::: "memory"); }
__device__ __forceinline__ void cp_wait0()  { asm volatile("cp.async.wait_group 0;" ::: "memory"); }
__device__ __forceinline__ void cp_wait1()  { asm volatile("cp.async.wait_group 1;" ::: "memory"); }
__device__ __forceinline__ void ldsm4(uint32_t* r, uint32_t addr) {
    asm volatile("ldmatrix.sync.aligned.m8n8.x4.shared.b16 {%0,%1,%2,%3}, [%4];"
                 : "=r"(r[0]), "=r"(r[1]), "=r"(r[2]), "=r"(r[3]) : "r"(addr));
}
__device__ __forceinline__ void ldsm4t(uint32_t* r, uint32_t addr) {
    asm volatile("ldmatrix.sync.aligned.m8n8.x4.trans.shared.b16 {%0,%1,%2,%3}, [%4];"
                 : "=r"(r[0]), "=r"(r[1]), "=r"(r[2]), "=r"(r[3]) : "r"(addr));
}
__device__ __forceinline__ void mma16816(float* d, const uint32_t* a, const uint32_t* b) {
    asm volatile(
        "mma.sync.aligned.m16n8k16.row.col.f32.bf16.bf16.f32 "
        "{%0,%1,%2,%3}, {%4,%5,%6,%7}, {%8,%9}, {%0,%1,%2,%3};"
        : "+f"(d[0]), "+f"(d[1]), "+f"(d[2]), "+f"(d[3])
        : "r"(a[0]), "r"(a[1]), "r"(a[2]), "r"(a[3]), "r"(b[0]), "r"(b[1]));
}

// ---------------- fused embedding + LN1 (layer 0) ----------------
__global__ void embed_ln_k(const int* __restrict__ x, const float* __restrict__ pos,
                           const float* __restrict__ g, const float* __restrict__ b)
{
    int r = blockIdx.x;
    int d = threadIdx.x;
    int t = r & (TT - 1);
    float v = pos[t * DD + d];
    if (d < VV) { float c = (float)d - (float)x[r]; v += -0.5f * c * c; }
    g_H[r * DD + d] = v;

    __shared__ float red[4];
    float s = v;
    #pragma unroll
    for (int o = 16; o; o >>= 1) s += __shfl_xor_sync(0xffffffffu, s, o);
    if ((d & 31) == 0) red[d >> 5] = s;
    __syncthreads();
    float mu = (red[0] + red[1] + red[2] + red[3]) * (1.f / DD);
    float dv = v - mu;
    float s2 = dv * dv;
    #pragma unroll
    for (int o = 16; o; o >>= 1) s2 += __shfl_xor_sync(0xffffffffu, s2, o);
    __syncthreads();
    if ((d & 31) == 0) red[d >> 5] = s2;
    __syncthreads();
    float var = (red[0] + red[1] + red[2] + red[3]) * (1.f / DD);
    g_H1b[r * DD + d] = __float2bfloat16(dv * rsqrtf(var + 1e-5f) * g[d] + b[d]);
}

// ---------------- all weight conversions ----------------
#define NQKV (LL*3*DD*DD)
#define NW1  (LL*HMM*DD)
#define NW2  (LL*DD*HMM)
__global__ void convall_k(const float* __restrict__ Wq, const float* __restrict__ Wk,
                          const float* __restrict__ Wv, const float* __restrict__ W1,
                          const float* __restrict__ W2)
{
    int i = blockIdx.x * blockDim.x + threadIdx.x;
    if (i < NQKV) {
        int l = i / (3 * DD * DD);
        int r = (i / DD) % (3 * DD);
        int d = i % DD;
        float v;
        if (r < 128)      v = Wq[((size_t)l * DD + r) * DD + d];
        else if (r < 256) v = Wk[((size_t)l * DD + r - 128) * DD + d];
        else              v = Wv[((size_t)l * DD + r - 256) * DD + d];
        g_Wqkvb[i] = __float2bfloat16(v);
    } else if (i < NQKV + NW1) {
        int j = i - NQKV;
        g_W1b[j] = __float2bfloat16(W1[j]);
    } else if (i < NQKV + NW1 + NW2) {
        int j = i - NQKV - NW1;
        g_W2b[j] = __float2bfloat16(W2[j]);
    }
}

// ---------------- single-shot K=128 GEMM (BM=128, BN=128, 256 thr) ----------------
#define GSTR 136
template<int EPI>
__global__ void __launch_bounds__(256)
gemm_ks(const __nv_bfloat16* __restrict__ A, const __nv_bfloat16* __restrict__ B,
        const float* __restrict__ bias, __nv_bfloat16* __restrict__ C,
        int ldc, float alpha)
{
    extern __shared__ __align__(16) char gsm[];
    const uint32_t sA = smem_u32(gsm);
    const uint32_t sB = sA + 128 * GSTR * 2;

    const int tid = threadIdx.x;
    const int lane = tid & 31;
    const int wid = tid >> 5;
    const int wm = (wid >> 2) * 64;
    const int wn = (wid & 3) * 32;
    const int m0 = blockIdx.x * 128;
    const int n0 = blockIdx.y * 128;

    {
        const int lrow = tid >> 1;
        const int base = (tid & 1) * 8;
        const __nv_bfloat16* ga = A + (long long)(m0 + lrow) * DD;
        const __nv_bfloat16* gb = B + (long long)(n0 + lrow) * DD;
        #pragma unroll
        for (int p = 0; p < 8; p++) {
            int col = base + p * 16;
            cp16(sA + (lrow * GSTR + col) * 2, ga + col);
            cp16(sB + (lrow * GSTR + col) * 2, gb + col);
        }
    }
    cp_commit();
    cp_wait0();
    __syncthreads();

    float acc[4][4][4];
    #pragma unroll
    for (int i = 0; i < 4; i++)
        #pragma unroll
        for (int j = 0; j < 4; j++)
            #pragma unroll
            for (int q = 0; q < 4; q++) acc[i][j][q] = 0.f;

    #pragma unroll
    for (int kk = 0; kk < 8; kk++) {
        uint32_t a[4][4];
        #pragma unroll
        for (int mi = 0; mi < 4; mi++)
            ldsm4(a[mi], sA + ((wm + mi * 16 + (lane & 15)) * GSTR
                               + kk * 16 + (lane >> 4) * 8) * 2);
        uint32_t b[4][2];
        #pragma unroll
        for (int bi = 0; bi < 2; bi++) {
            uint32_t r[4];
            ldsm4(r, sB + ((wn + bi * 16 + (lane >> 4) * 8 + (lane & 7)) * GSTR
                           + kk * 16 + (lane & 8)) * 2);
            b[2 * bi][0] = r[0]; b[2 * bi][1] = r[1];
            b[2 * bi + 1][0] = r[2]; b[2 * bi + 1][1] = r[3];
        }
        #pragma unroll
        for (int mi = 0; mi < 4; mi++)
            #pragma unroll
            for (int ni = 0; ni < 4; ni++)
                mma16816(acc[mi][ni], a[mi], b[ni]);
    }

    const int g = lane >> 2, tg = lane & 3;
    const float aa = (EPI == 6 && n0 != 0) ? 1.f : alpha;
    #pragma unroll
    for (int mi = 0; mi < 4; mi++) {
        #pragma unroll
        for (int ni = 0; ni < 4; ni++) {
            const int row = m0 + wm + mi * 16 + g;
            const int col = n0 + wn + ni * 8 + tg * 2;
            float c0 = acc[mi][ni][0] * aa, c1 = acc[mi][ni][1] * aa;
            float c2 = acc[mi][ni][2] * aa, c3 = acc[mi][ni][3] * aa;
            if (EPI == 3) {
                float b0 = bias[col], b1 = bias[col + 1];
                c0 += b0; c1 += b1; c2 += b0; c3 += b1;
                c0 = 0.5f * c0 * (1.f + erff(c0 * 0.70710678f));
                c1 = 0.5f * c1 * (1.f + erff(c1 * 0.70710678f));
                c2 = 0.5f * c2 * (1.f + erff(c2 * 0.70710678f));
                c3 = 0.5f * c3 * (1.f + erff(c3 * 0.70710678f));
                *(__nv_bfloat162*)&C[(long long)row * ldc + col] =
                    __float22bfloat162_rn(make_float2(c0, c1));
                *(__nv_bfloat162*)&C[(long long)(row + 8) * ldc + col] =
                    __float22bfloat162_rn(make_float2(c2, c3));
            } else {  // EPI 6
                __nv_bfloat16* Ct = (n0 == 0) ? g_Qb : (n0 == 128) ? g_Kb : g_Vb;
                const int cc = col & 127;
                *(__nv_bfloat162*)&Ct[(long long)row * DD + cc] =
                    __float22bfloat162_rn(make_float2(c0, c1));
                *(__nv_bfloat162*)&Ct[(long long)(row + 8) * DD + cc] =
                    __float22bfloat162_rn(make_float2(c2, c3));
            }
        }
    }
}

// ---------------- MLP2 + residual + LN1(next layer) ----------------
__global__ void __launch_bounds__(256)
mlp2_k(const __nv_bfloat16* __restrict__ A, const __nv_bfloat16* __restrict__ W,
       const float* __restrict__ bias, float* __restrict__ H,
       const float* __restrict__ lng, const float* __restrict__ lnb)
{
    __shared__ __align__(16) __nv_bfloat16 Asm[2][64 * 40];
    __shared__ __align__(16) __nv_bfloat16 Bsm[2][128 * 40];
    __shared__ float rs[64][4];

    const int tid = threadIdx.x;
    const int lane = tid & 31;
    const int wid = tid >> 5;
    const int wm = (wid >> 2) * 32;
    const int nw = wid & 3;
    const int wn = nw * 32;
    const int m0 = blockIdx.x * 64;

    float acc[2][4][4];
    #pragma unroll
    for (int i = 0; i < 2; i++)
        #pragma unroll
        for (int j = 0; j < 4; j++)
            #pragma unroll
            for (int q = 0; q < 4; q++) acc[i][j][q] = 0.f;

    const int lrow = tid >> 2;
    const int lcol = (tid & 3) * 8;

    auto load_tile = [&](int c, int buf) {
        const int k0 = c * 32;
        cp16(smem_u32(&Asm[buf][lrow * 40 + lcol]),
             A + (long long)(m0 + lrow) * HMM + k0 + lcol);
        cp16(smem_u32(&Bsm[buf][lrow * 40 + lcol]),
             W + (long long)lrow * HMM + k0 + lcol);
        cp16(smem_u32(&Bsm[buf][(lrow + 64) * 40 + lcol]),
             W + (long long)(lrow + 64) * HMM + k0 + lcol);
        cp_commit();
    };

    load_tile(0, 0);
    for (int c = 0; c < 16; c++) {
        const int buf = c & 1;
        if (c + 1 < 16) { load_tile(c + 1, buf ^ 1); cp_wait1(); }
        else            { cp_wait0(); }
        __syncthreads();
        uint32_t aBase = smem_u32(&Asm[buf][0]);
        uint32_t bBase = smem_u32(&Bsm[buf][0]);
        #pragma unroll
        for (int kk = 0; kk < 2; kk++) {
            uint32_t a[2][4];
            #pragma unroll
            for (int mi = 0; mi < 2; mi++)
                ldsm4(a[mi], aBase + ((wm + mi * 16 + (lane & 15)) * 40
                                      + kk * 16 + (lane >> 4) * 8) * 2);
            uint32_t b[4][2];
            #pragma unroll
            for (int bi = 0; bi < 2; bi++) {
                uint32_t r[4];
                ldsm4(r, bBase + ((wn + bi * 16 + (lane >> 4) * 8 + (lane & 7)) * 40
                                  + kk * 16 + (lane & 8)) * 2);
                b[2 * bi][0] = r[0]; b[2 * bi][1] = r[1];
                b[2 * bi + 1][0] = r[2]; b[2 * bi + 1][1] = r[3];
            }
            #pragma unroll
            for (int mi = 0; mi < 2; mi++)
                #pragma unroll
                for (int ni = 0; ni < 4; ni++)
                    mma16816(acc[mi][ni], a[mi], b[ni]);
        }
        __syncthreads();
    }

    const int g = lane >> 2, tg = lane & 3;
    float v[2][2][4][2];
    #pragma unroll
    for (int mi = 0; mi < 2; mi++) {
        const int row = m0 + wm + mi * 16 + g;
        #pragma unroll
        for (int ni = 0; ni < 4; ni++) {
            const int col = wn + ni * 8 + tg * 2;
            const float b0 = bias[col], b1 = bias[col + 1];
            float2* p = (float2*)&H[(long long)row * DD + col];
            float2 h = *p;
            h.x += acc[mi][ni][0] + b0; h.y += acc[mi][ni][1] + b1;
            *p = h; v[mi][0][ni][0] = h.x; v[mi][0][ni][1] = h.y;
            p = (float2*)&H[(long long)(row + 8) * DD + col];
            h = *p;
            h.x += acc[mi][ni][2] + b0; h.y += acc[mi][ni][3] + b1;
            *p = h; v[mi][1][ni][0] = h.x; v[mi][1][ni][1] = h.y;
        }
    }
    #pragma unroll
    for (int mi = 0; mi < 2; mi++)
        #pragma unroll
        for (int rh = 0; rh < 2; rh++) {
            float s = 0.f;
            #pragma unroll
            for (int ni = 0; ni < 4; ni++) s += v[mi][rh][ni][0] + v[mi][rh][ni][1];
            s += __shfl_xor_sync(0xffffffffu, s, 1);
            s += __shfl_xor_sync(0xffffffffu, s, 2);
            if (tg == 0) rs[wm + mi * 16 + rh * 8 + g][nw] = s;
        }
    __syncthreads();
    float mu[2][2];
    #pragma unroll
    for (int mi = 0; mi < 2; mi++)
        #pragma unroll
        for (int rh = 0; rh < 2; rh++) {
            const int lr = wm + mi * 16 + rh * 8 + g;
            mu[mi][rh] = (rs[lr][0] + rs[lr][1] + rs[lr][2] + rs[lr][3]) * (1.f / DD);
        }
    __syncthreads();
    #pragma unroll
    for (int mi = 0; mi < 2; mi++)
        #pragma unroll
        for (int rh = 0; rh < 2; rh++) {
            float s = 0.f;
            #pragma unroll
            for (int ni = 0; ni < 4; ni++) {
                float d0 = v[mi][rh][ni][0] - mu[mi][rh];
                float d1 = v[mi][rh][ni][1] - mu[mi][rh];
                s += d0 * d0 + d1 * d1;
            }
            s += __shfl_xor_sync(0xffffffffu, s, 1);
            s += __shfl_xor_sync(0xffffffffu, s, 2);
            if (tg == 0) rs[wm + mi * 16 + rh * 8 + g][nw] = s;
        }
    __syncthreads();
    #pragma unroll
    for (int mi = 0; mi < 2; mi++) {
        #pragma unroll
        for (int rh = 0; rh < 2; rh++) {
            const int lr = wm + mi * 16 + rh * 8 + g;
            const float var = (rs[lr][0] + rs[lr][1] + rs[lr][2] + rs[lr][3]) * (1.f / DD);
            const float rsg = rsqrtf(var + 1e-5f);
            const long long row = m0 + lr;
            #pragma unroll
            for (int ni = 0; ni < 4; ni++) {
                const int col = wn + ni * 8 + tg * 2;
                *(__nv_bfloat162*)&g_H1b[row * DD + col] = __float22bfloat162_rn(make_float2(
                    (v[mi][rh][ni][0] - mu[mi][rh]) * rsg * lng[col] + lnb[col],
                    (v[mi][rh][ni][1] - mu[mi][rh]) * rsg * lng[col + 1] + lnb[col + 1]));
            }
        }
    }
}

// ---------------- flash v3: 8 warps, S columns split across 2 warp groups ----------------
// Q pre-scaled by log2(e)/sqrt(D); softmax numerator = exp2(s) (no max, logits O(1)).
// Group g computes S[:, g*64:(g+1)*64] and its partial PV; merge is a pure add.
#define FSTR 136
#define QS_OFF   0
#define KS_OFF   17408
#define VS_OFF   (17408 + 2*34816)
#define FLASH_SMEM (17408 + 4*34816)   // 156672

__global__ void __launch_bounds__(256, 1)
flash_k(const __nv_bfloat16* __restrict__ Q, const __nv_bfloat16* __restrict__ K,
        const __nv_bfloat16* __restrict__ V, float* __restrict__ H,
        const float* __restrict__ lng, const float* __restrict__ lnb)
{
    extern __shared__ __align__(16) char fsm[];
    const int tid = threadIdx.x;
    const int lane = tid & 31;
    const int wid = tid >> 5;
    const int grp = wid >> 2;            // 0/1: S-column half
    const int wm = (wid & 3) * 16;       // Q rows for this warp
    const int kco = grp * 64;            // K/V row offset within a 128-row tile
    const int b = blockIdx.y;
    const int m0 = blockIdx.x * 64;

    const uint32_t sQ = smem_u32(fsm) + QS_OFF;
    const uint32_t sK0 = smem_u32(fsm) + KS_OFF;
    const uint32_t sV0 = smem_u32(fsm) + VS_OFF;

    const __nv_bfloat16* Qg = Q + ((long long)b * TT + m0) * DD;
    const __nv_bfloat16* Kg = K + (long long)b * TT * DD;
    const __nv_bfloat16* Vg = V + (long long)b * TT * DD;

    // Q load: 256 threads cover 64x128
    {
        const int row = tid >> 2;
        const int cb = (tid & 3) * 8;
        #pragma unroll
        for (int p = 0; p < 4; p++)
            cp16(sQ + (row * FSTR + cb + p * 32) * 2, Qg + (long long)row * DD + cb + p * 32);
    }
    cp_commit();

    const int lrow = tid >> 4;           // 0..15
    const int lch = (tid & 15) * 8;
    auto loadKV = [&](int c, int buf) {
        const __nv_bfloat16* kg = Kg + (long long)c * 128 * DD;
        const __nv_bfloat16* vg = Vg + (long long)c * 128 * DD;
        uint32_t dk = sK0 + buf * 34816;
        uint32_t dv = sV0 + buf * 34816;
        #pragma unroll
        for (int p = 0; p < 8; p++) {
            int row = lrow + p * 16;
            cp16(dk + (row * FSTR + lch) * 2, kg + (long long)row * DD + lch);
            cp16(dv + (row * FSTR + lch) * 2, vg + (long long)row * DD + lch);
        }
        cp_commit();
    };

    loadKV(0, 0);
    cp_wait1();          // Q group retired
    __syncthreads();

    uint32_t aq[8][4];
    #pragma unroll
    for (int kk = 0; kk < 8; kk++)
        ldsm4(aq[kk], sQ + ((wm + (lane & 15)) * FSTR + kk * 16 + (lane >> 4) * 8) * 2);

    float oa[16][4];
    #pragma unroll
    for (int j = 0; j < 16; j++)
        #pragma unroll
        for (int q = 0; q < 4; q++) oa[j][q] = 0.f;
    float l0 = 0.f, l1 = 0.f;

    const int NKV = TT / 128;
    for (int c = 0; c < NKV; c++) {
        const int buf = c & 1;
        if (c + 1 < NKV) { loadKV(c + 1, buf ^ 1); cp_wait1(); }
        else            { cp_wait0(); }
        __syncthreads();

        const uint32_t kB = sK0 + buf * 34816;
        const uint32_t vB = sV0 + buf * 34816;

        // ---- S half: 16 rows x 64 cols ----
        float sa[8][4];
        #pragma unroll
        for (int j = 0; j < 8; j++)
            #pragma unroll
            for (int q = 0; q < 4; q++) sa[j][q] = 0.f;

        #pragma unroll
        for (int kk = 0; kk < 8; kk++) {
            #pragma unroll
            for (int bi = 0; bi < 4; bi++) {
                uint32_t r[4];
                ldsm4(r, kB + ((kco + bi * 16 + (lane >> 4) * 8 + (lane & 7)) * FSTR
                               + kk * 16 + (lane & 8)) * 2);
                uint32_t b0[2] = { r[0], r[1] }, b1[2] = { r[2], r[3] };
                mma16816(sa[2 * bi], aq[kk], b0);
                mma16816(sa[2 * bi + 1], aq[kk], b1);
            }
        }

        // ---- p = exp2(s) (Q carries log2e), accumulate l per-thread ----
        uint32_t pa[4][4];
        #pragma unroll
        for (int kk = 0; kk < 4; kk++) {
            float p00 = exp2f(sa[2*kk][0]),   p01 = exp2f(sa[2*kk][1]);
            float p02 = exp2f(sa[2*kk][2]),   p03 = exp2f(sa[2*kk][3]);
            float p10 = exp2f(sa[2*kk+1][0]), p11 = exp2f(sa[2*kk+1][1]);
            float p12 = exp2f(sa[2*kk+1][2]), p13 = exp2f(sa[2*kk+1][3]);
            l0 += p00 + p01 + p10 + p11;
            l1 += p02 + p03 + p12 + p13;
            __nv_bfloat162 h;
            h = __float22bfloat162_rn(make_float2(p00, p01)); pa[kk][0] = *(uint32_t*)&h;
            h = __float22bfloat162_rn(make_float2(p02, p03)); pa[kk][1] = *(uint32_t*)&h;
            h = __float22bfloat162_rn(make_float2(p10, p11)); pa[kk][2] = *(uint32_t*)&h;
            h = __float22bfloat162_rn(make_float2(p12, p13)); pa[kk][3] = *(uint32_t*)&h;
        }

        // ---- O_partial += P_half @ V[group rows] ----
        #pragma unroll
        for (int kk = 0; kk < 4; kk++) {
            #pragma unroll
            for (int bi = 0; bi < 8; bi++) {
                uint32_t r[4];
                ldsm4t(r, vB + ((kco + kk * 16 + (lane & 15)) * FSTR
                                + bi * 16 + (lane >> 4) * 8) * 2);
                uint32_t b0[2] = { r[0], r[1] }, b1[2] = { r[2], r[3] };
                mma16816(oa[2 * bi], pa[kk], b0);
                mma16816(oa[2 * bi + 1], pa[kk], b1);
            }
        }
        __syncthreads();
    }

    // quad reduce of l partials
    l0 += __shfl_xor_sync(0xffffffffu, l0, 1);
    l0 += __shfl_xor_sync(0xffffffffu, l0, 2);
    l1 += __shfl_xor_sync(0xffffffffu, l1, 1);
    l1 += __shfl_xor_sync(0xffffffffu, l1, 2);

    // ---- merge groups (pure add) via smem reuse ----
    const int g = lane >> 2, tg = lane & 3;
    float* exch = (float*)(fsm + KS_OFF);              // [64][128] fp32
    float* lsum = (float*)(fsm + KS_OFF + 64*128*4);   // [64][2]
    if (grp == 1) {
        #pragma unroll
        for (int j = 0; j < 16; j++) {
            const int col = j * 8 + tg * 2;
            exch[(wm + g) * 128 + col]         = oa[j][0];
            exch[(wm + g) * 128 + col + 1]     = oa[j][1];
            exch[(wm + 8 + g) * 128 + col]     = oa[j][2];
            exch[(wm + 8 + g) * 128 + col + 1] = oa[j][3];
        }
        if (tg == 0) {
            lsum[(wm + g) * 2]     = l0;
            lsum[(wm + 8 + g) * 2] = l1;
        }
    }
    __syncthreads();
    if (grp == 0) {
        l0 += lsum[(wm + g) * 2];
        l1 += lsum[(wm + 8 + g) * 2];
        #pragma unroll
        for (int j = 0; j < 16; j++) {
            const int col = j * 8 + tg * 2;
            oa[j][0] += exch[(wm + g) * 128 + col];
            oa[j][1] += exch[(wm + g) * 128 + col + 1];
            oa[j][2] += exch[(wm + 8 + g) * 128 + col];
            oa[j][3] += exch[(wm + 8 + g) * 128 + col + 1];
        }

        // ---- epilogue: H += O/l, then LN2 -> H1b ----
        const float inv0 = 1.f / l0, inv1 = 1.f / l1;
        const long long row0 = (long long)b * TT + m0 + wm + g;
        float s0 = 0.f, s1 = 0.f;
        #pragma unroll
        for (int j = 0; j < 16; j++) {
            const int col = j * 8 + tg * 2;
            float2* p = (float2*)&H[row0 * DD + col];
            float2 v = *p;
            v.x += oa[j][0] * inv0; v.y += oa[j][1] * inv0;
            *p = v; oa[j][0] = v.x; oa[j][1] = v.y;
            s0 += v.x + v.y;
            p = (float2*)&H[(row0 + 8) * DD + col];
            v = *p;
            v.x += oa[j][2] * inv1; v.y += oa[j][3] * inv1;
            *p = v; oa[j][2] = v.x; oa[j][3] = v.y;
            s1 += v.x + v.y;
        }
        s0 += __shfl_xor_sync(0xffffffffu, s0, 1);
        s0 += __shfl_xor_sync(0xffffffffu, s0, 2);
        s1 += __shfl_xor_sync(0xffffffffu, s1, 1);
        s1 += __shfl_xor_sync(0xffffffffu, s1, 2);
        const float mu0 = s0 * (1.f / DD), mu1 = s1 * (1.f / DD);
        float q0 = 0.f, q1 = 0.f;
        #pragma unroll
        for (int j = 0; j < 16; j++) {
            float d0 = oa[j][0] - mu0, d1 = oa[j][1] - mu0;
            q0 += d0 * d0 + d1 * d1;
            float d2 = oa[j][2] - mu1, d3 = oa[j][3] - mu1;
            q1 += d2 * d2 + d3 * d3;
        }
        q0 += __shfl_xor_sync(0xffffffffu, q0, 1);
        q0 += __shfl_xor_sync(0xffffffffu, q0, 2);
        q1 += __shfl_xor_sync(0xffffffffu, q1, 1);
        q1 += __shfl_xor_sync(0xffffffffu, q1, 2);
        const float rs0 = rsqrtf(q0 * (1.f / DD) + 1e-5f);
        const float rs1 = rsqrtf(q1 * (1.f / DD) + 1e-5f);
        #pragma unroll
        for (int j = 0; j < 16; j++) {
            const int col = j * 8 + tg * 2;
            const float ga = lng[col], gb2 = lng[col + 1];
            const float ba = lnb[col], bb2 = lnb[col + 1];
            *(__nv_bfloat162*)&g_H1b[row0 * DD + col] = __float22bfloat162_rn(make_float2(
                (oa[j][0] - mu0) * rs0 * ga + ba, (oa[j][1] - mu0) * rs0 * gb2 + bb2));
            *(__nv_bfloat162*)&g_H1b[(row0 + 8) * DD + col] = __float22bfloat162_rn(make_float2(
                (oa[j][2] - mu1) * rs1 * ga + ba, (oa[j][3] - mu1) * rs1 * gb2 + bb2));
        }
    }
}

// ---------------- readout ----------------
__global__ void readout_k(const float* __restrict__ Wro, const float* __restrict__ bro,
                          float* __restrict__ out)
{
    int r = blockIdx.x * 8 + (threadIdx.x >> 5);
    int lane = threadIdx.x & 31;
    float4 h = *(const float4*)&g_H[r * DD + lane * 4];
    float4 w = *(const float4*)&Wro[lane * 4];
    float s = h.x * w.x + h.y * w.y + h.z * w.z + h.w * w.w;
    #pragma unroll
    for (int o = 16; o; o >>= 1) s += __shfl_xor_sync(0xffffffffu, s, o);
    if (lane == 0) out[r] = s + bro[0];
}

// ---------------- host launcher ----------------
extern "C" void kernel_launch(void* const* d_in, const int* in_sizes, int n_in,
                              void* d_out, int out_size)
{
    (void)in_sizes; (void)n_in; (void)out_size;
    const int*   x    = (const int*)  d_in[0];
    const float* pos  = (const float*)d_in[1];
    const float* Wq   = (const float*)d_in[2];
    const float* Wk   = (const float*)d_in[3];
    const float* Wv   = (const float*)d_in[4];
    const float* ln1g = (const float*)d_in[5];
    const float* ln1b = (const float*)d_in[6];
    const float* W1   = (const float*)d_in[7];
    const float* b1   = (const float*)d_in[8];
    const float* W2   = (const float*)d_in[9];
    const float* b2   = (const float*)d_in[10];
    const float* ln2g = (const float*)d_in[11];
    const float* ln2b = (const float*)d_in[12];
    const float* Wro  = (const float*)d_in[13];
    const float* bro  = (const float*)d_in[14];
    float* out = (float*)d_out;

    float *pH; __nv_bfloat16 *pH1b, *pQb, *pKb, *pVb, *pM1b;
    __nv_bfloat16 *pWqkvb, *pW1b, *pW2b;
    cudaGetSymbolAddress((void**)&pH,    g_H);
    cudaGetSymbolAddress((void**)&pH1b,  g_H1b);
    cudaGetSymbolAddress((void**)&pQb,   g_Qb);
    cudaGetSymbolAddress((void**)&pKb,   g_Kb);
    cudaGetSymbolAddress((void**)&pVb,   g_Vb);
    cudaGetSymbolAddress((void**)&pM1b,  g_M1b);
    cudaGetSymbolAddress((void**)&pWqkvb, g_Wqkvb);
    cudaGetSymbolAddress((void**)&pW1b,  g_W1b);
    cudaGetSymbolAddress((void**)&pW2b,  g_W2b);

    const int GS_SMEM = 2 * 128 * GSTR * 2;   // 69632
    cudaFuncSetAttribute(flash_k, cudaFuncAttributeMaxDynamicSharedMemorySize, FLASH_SMEM);
    cudaFuncSetAttribute(gemm_ks<6>, cudaFuncAttributeMaxDynamicSharedMemorySize, GS_SMEM);
    cudaFuncSetAttribute(gemm_ks<3>, cudaFuncAttributeMaxDynamicSharedMemorySize, GS_SMEM);

    // Q pre-scale folds 1/sqrt(D) and log2(e) so flash uses bare exp2
    const float q_scale = (1.f / sqrtf((float)DD)) * 1.4426950408889634f;

    convall_k<<<(NQKV + NW1 + NW2 + 255) / 256, 256>>>(Wq, Wk, Wv, W1, W2);
    embed_ln_k<<<BTT, 128>>>(x, pos, ln1g, ln1b);

    for (int l = 0; l < LL; l++) {
        {
            dim3 g(BTT/128, 3, 1);
            gemm_ks<6><<<g, 256, GS_SMEM>>>(pH1b, pWqkvb + (size_t)l*3*DD*DD, nullptr,
                                            nullptr, DD, q_scale);
        }
        {
            dim3 g(TT/64, BB);
            flash_k<<<g, 256, FLASH_SMEM>>>(pQb, pKb, pVb, pH, ln2g + l*DD, ln2b + l*DD);
        }
        {
            dim3 g(BTT/128, HMM/128, 1);
            gemm_ks<3><<<g, 256, GS_SMEM>>>(pH1b, pW1b + (size_t)l*HMM*DD, b1 + (size_t)l*HMM,
                                            pM1b, HMM, 1.f);
        }
        {
            const int ln = (l + 1) % LL;
            mlp2_k<<<BTT/64, 256>>>(pM1b, pW2b + (size_t)l*DD*HMM, b2 + (size_t)l*DD,
                                    pH, ln1g + (size_t)ln*DD, ln1b + (size_t)ln*DD);
        }
    }

    readout_k<<<BTT / 8, 256>>>(Wro, bro, out);
}

// round 11
// speedup vs baseline: 1.5747x; 1.5747x over previous
#include <cuda_runtime.h>
#include <cuda_bf16.h>
#include <math.h>
#include <stdint.h>

#define BB  4
#define TT  2048
#define DD  128
#define VV  64
#define LL  12
#define HMM 512
#define BTT (BB*TT)   // 8192

// ---------------- scratch ----------------
__device__ float          g_H  [BTT*DD];
__device__ __nv_bfloat16  g_H1b[BTT*DD];
__device__ __nv_bfloat16  g_Qb [BTT*DD];
__device__ __nv_bfloat16  g_Kb [BTT*DD];
__device__ __nv_bfloat16  g_Vb [BTT*DD];
__device__ __nv_bfloat16  g_M1b[BTT*HMM];
__device__ __nv_bfloat16  g_Wqkvb[LL*3*DD*DD];
__device__ __nv_bfloat16  g_W1b[LL*HMM*DD];
__device__ __nv_bfloat16  g_W2b[LL*DD*HMM];

// ---------------- helpers ----------------
__device__ __forceinline__ uint32_t smem_u32(const void* p) {
    uint32_t a;
    asm("{ .reg .u64 t; cvta.to.shared.u64 t, %1; cvt.u32.u64 %0, t; }" : "=r"(a) : "l"(p));
    return a;
}
__device__ __forceinline__ void cp16(uint32_t saddr, const void* gaddr) {
    asm volatile("cp.async.cg.shared.global [%0], [%1], 16;" :: "r"(saddr), "l"(gaddr) : "memory");
}
__device__ __forceinline__ void cp_commit() { asm volatile("cp.async.commit_group;" ::: "memory"); }
__device__ __forceinline__ void cp_wait0()  { asm volatile("cp.async.wait_group 0;" ::: "memory"); }
__device__ __forceinline__ void cp_wait1()  { asm volatile("cp.async.wait_group 1;" ::: "memory"); }
__device__ __forceinline__ void ldsm4(uint32_t* r, uint32_t addr) {
    asm volatile("ldmatrix.sync.aligned.m8n8.x4.shared.b16 {%0,%1,%2,%3}, [%4];"
                 : "=r"(r[0]), "=r"(r[1]), "=r"(r[2]), "=r"(r[3]) : "r"(addr));
}
__device__ __forceinline__ void ldsm4t(uint32_t* r, uint32_t addr) {
    asm volatile("ldmatrix.sync.aligned.m8n8.x4.trans.shared.b16 {%0,%1,%2,%3}, [%4];"
                 : "=r"(r[0]), "=r"(r[1]), "=r"(r[2]), "=r"(r[3]) : "r"(addr));
}
__device__ __forceinline__ void mma16816(float* d, const uint32_t* a, const uint32_t* b) {
    asm volatile(
        "mma.sync.aligned.m16n8k16.row.col.f32.bf16.bf16.f32 "
        "{%0,%1,%2,%3}, {%4,%5,%6,%7}, {%8,%9}, {%0,%1,%2,%3};"
        : "+f"(d[0]), "+f"(d[1]), "+f"(d[2]), "+f"(d[3])
        : "r"(a[0]), "r"(a[1]), "r"(a[2]), "r"(a[3]), "r"(b[0]), "r"(b[1]));
}

// ---------------- fused embedding + LN1 (layer 0) ----------------
__global__ void embed_ln_k(const int* __restrict__ x, const float* __restrict__ pos,
                           const float* __restrict__ g, const float* __restrict__ b)
{
    int r = blockIdx.x;
    int d = threadIdx.x;
    int t = r & (TT - 1);
    float v = pos[t * DD + d];
    if (d < VV) { float c = (float)d - (float)x[r]; v += -0.5f * c * c; }
    g_H[r * DD + d] = v;

    __shared__ float red[4];
    float s = v;
    #pragma unroll
    for (int o = 16; o; o >>= 1) s += __shfl_xor_sync(0xffffffffu, s, o);
    if ((d & 31) == 0) red[d >> 5] = s;
    __syncthreads();
    float mu = (red[0] + red[1] + red[2] + red[3]) * (1.f / DD);
    float dv = v - mu;
    float s2 = dv * dv;
    #pragma unroll
    for (int o = 16; o; o >>= 1) s2 += __shfl_xor_sync(0xffffffffu, s2, o);
    __syncthreads();
    if ((d & 31) == 0) red[d >> 5] = s2;
    __syncthreads();
    float var = (red[0] + red[1] + red[2] + red[3]) * (1.f / DD);
    g_H1b[r * DD + d] = __float2bfloat16(dv * rsqrtf(var + 1e-5f) * g[d] + b[d]);
}

// ---------------- all weight conversions ----------------
#define NQKV (LL*3*DD*DD)
#define NW1  (LL*HMM*DD)
#define NW2  (LL*DD*HMM)
__global__ void convall_k(const float* __restrict__ Wq, const float* __restrict__ Wk,
                          const float* __restrict__ Wv, const float* __restrict__ W1,
                          const float* __restrict__ W2)
{
    int i = blockIdx.x * blockDim.x + threadIdx.x;
    if (i < NQKV) {
        int l = i / (3 * DD * DD);
        int r = (i / DD) % (3 * DD);
        int d = i % DD;
        float v;
        if (r < 128)      v = Wq[((size_t)l * DD + r) * DD + d];
        else if (r < 256) v = Wk[((size_t)l * DD + r - 128) * DD + d];
        else              v = Wv[((size_t)l * DD + r - 256) * DD + d];
        g_Wqkvb[i] = __float2bfloat16(v);
    } else if (i < NQKV + NW1) {
        int j = i - NQKV;
        g_W1b[j] = __float2bfloat16(W1[j]);
    } else if (i < NQKV + NW1 + NW2) {
        int j = i - NQKV - NW1;
        g_W2b[j] = __float2bfloat16(W2[j]);
    }
}

// ---------------- single-shot K=128 GEMM (BM=128, BN=128, 256 thr) ----------------
#define GSTR 136
template<int EPI>
__global__ void __launch_bounds__(256)
gemm_ks(const __nv_bfloat16* __restrict__ A, const __nv_bfloat16* __restrict__ B,
        const float* __restrict__ bias, __nv_bfloat16* __restrict__ C,
        int ldc, float alpha)
{
    extern __shared__ __align__(16) char gsm[];
    const uint32_t sA = smem_u32(gsm);
    const uint32_t sB = sA + 128 * GSTR * 2;

    const int tid = threadIdx.x;
    const int lane = tid & 31;
    const int wid = tid >> 5;
    const int wm = (wid >> 2) * 64;
    const int wn = (wid & 3) * 32;
    const int m0 = blockIdx.x * 128;
    const int n0 = blockIdx.y * 128;

    {
        const int lrow = tid >> 1;
        const int base = (tid & 1) * 8;
        const __nv_bfloat16* ga = A + (long long)(m0 + lrow) * DD;
        const __nv_bfloat16* gb = B + (long long)(n0 + lrow) * DD;
        #pragma unroll
        for (int p = 0; p < 8; p++) {
            int col = base + p * 16;
            cp16(sA + (lrow * GSTR + col) * 2, ga + col);
            cp16(sB + (lrow * GSTR + col) * 2, gb + col);
        }
    }
    cp_commit();
    cp_wait0();
    __syncthreads();

    float acc[4][4][4];
    #pragma unroll
    for (int i = 0; i < 4; i++)
        #pragma unroll
        for (int j = 0; j < 4; j++)
            #pragma unroll
            for (int q = 0; q < 4; q++) acc[i][j][q] = 0.f;

    #pragma unroll
    for (int kk = 0; kk < 8; kk++) {
        uint32_t a[4][4];
        #pragma unroll
        for (int mi = 0; mi < 4; mi++)
            ldsm4(a[mi], sA + ((wm + mi * 16 + (lane & 15)) * GSTR
                               + kk * 16 + (lane >> 4) * 8) * 2);
        uint32_t b[4][2];
        #pragma unroll
        for (int bi = 0; bi < 2; bi++) {
            uint32_t r[4];
            ldsm4(r, sB + ((wn + bi * 16 + (lane >> 4) * 8 + (lane & 7)) * GSTR
                           + kk * 16 + (lane & 8)) * 2);
            b[2 * bi][0] = r[0]; b[2 * bi][1] = r[1];
            b[2 * bi + 1][0] = r[2]; b[2 * bi + 1][1] = r[3];
        }
        #pragma unroll
        for (int mi = 0; mi < 4; mi++)
            #pragma unroll
            for (int ni = 0; ni < 4; ni++)
                mma16816(acc[mi][ni], a[mi], b[ni]);
    }

    const int g = lane >> 2, tg = lane & 3;
    const float aa = (EPI == 6 && n0 != 0) ? 1.f : alpha;
    #pragma unroll
    for (int mi = 0; mi < 4; mi++) {
        #pragma unroll
        for (int ni = 0; ni < 4; ni++) {
            const int row = m0 + wm + mi * 16 + g;
            const int col = n0 + wn + ni * 8 + tg * 2;
            float c0 = acc[mi][ni][0] * aa, c1 = acc[mi][ni][1] * aa;
            float c2 = acc[mi][ni][2] * aa, c3 = acc[mi][ni][3] * aa;
            if (EPI == 3) {
                float b0 = bias[col], b1 = bias[col + 1];
                c0 += b0; c1 += b1; c2 += b0; c3 += b1;
                c0 = 0.5f * c0 * (1.f + erff(c0 * 0.70710678f));
                c1 = 0.5f * c1 * (1.f + erff(c1 * 0.70710678f));
                c2 = 0.5f * c2 * (1.f + erff(c2 * 0.70710678f));
                c3 = 0.5f * c3 * (1.f + erff(c3 * 0.70710678f));
                *(__nv_bfloat162*)&C[(long long)row * ldc + col] =
                    __float22bfloat162_rn(make_float2(c0, c1));
                *(__nv_bfloat162*)&C[(long long)(row + 8) * ldc + col] =
                    __float22bfloat162_rn(make_float2(c2, c3));
            } else {  // EPI 6
                __nv_bfloat16* Ct = (n0 == 0) ? g_Qb : (n0 == 128) ? g_Kb : g_Vb;
                const int cc = col & 127;
                *(__nv_bfloat162*)&Ct[(long long)row * DD + cc] =
                    __float22bfloat162_rn(make_float2(c0, c1));
                *(__nv_bfloat162*)&Ct[(long long)(row + 8) * DD + cc] =
                    __float22bfloat162_rn(make_float2(c2, c3));
            }
        }
    }
}

// ---------------- MLP2 + residual + LN1(next layer), BK=64 ----------------
#define MSTR 72
__global__ void __launch_bounds__(256)
mlp2_k(const __nv_bfloat16* __restrict__ A, const __nv_bfloat16* __restrict__ W,
       const float* __restrict__ bias, float* __restrict__ H,
       const float* __restrict__ lng, const float* __restrict__ lnb)
{
    __shared__ __align__(16) __nv_bfloat16 Asm[2][64 * MSTR];
    __shared__ __align__(16) __nv_bfloat16 Bsm[2][128 * MSTR];
    __shared__ float rs[64][4];

    const int tid = threadIdx.x;
    const int lane = tid & 31;
    const int wid = tid >> 5;
    const int wm = (wid >> 2) * 32;
    const int nw = wid & 3;
    const int wn = nw * 32;
    const int m0 = blockIdx.x * 64;

    float acc[2][4][4];
    #pragma unroll
    for (int i = 0; i < 2; i++)
        #pragma unroll
        for (int j = 0; j < 4; j++)
            #pragma unroll
            for (int q = 0; q < 4; q++) acc[i][j][q] = 0.f;

    const int lrow = tid >> 3;          // 0..31
    const int lcol = (tid & 7) * 8;     // 0..56 halves

    auto load_tile = [&](int c, int buf) {
        const int k0 = c * 64;
        #pragma unroll
        for (int p = 0; p < 2; p++) {
            int row = lrow + p * 32;
            cp16(smem_u32(&Asm[buf][row * MSTR + lcol]),
                 A + (long long)(m0 + row) * HMM + k0 + lcol);
        }
        #pragma unroll
        for (int p = 0; p < 4; p++) {
            int row = lrow + p * 32;
            cp16(smem_u32(&Bsm[buf][row * MSTR + lcol]),
                 W + (long long)row * HMM + k0 + lcol);
        }
        cp_commit();
    };

    load_tile(0, 0);
    for (int c = 0; c < 8; c++) {
        const int buf = c & 1;
        if (c + 1 < 8) { load_tile(c + 1, buf ^ 1); cp_wait1(); }
        else           { cp_wait0(); }
        __syncthreads();
        uint32_t aBase = smem_u32(&Asm[buf][0]);
        uint32_t bBase = smem_u32(&Bsm[buf][0]);
        #pragma unroll
        for (int kk = 0; kk < 4; kk++) {
            uint32_t a[2][4];
            #pragma unroll
            for (int mi = 0; mi < 2; mi++)
                ldsm4(a[mi], aBase + ((wm + mi * 16 + (lane & 15)) * MSTR
                                      + kk * 16 + (lane >> 4) * 8) * 2);
            uint32_t b[4][2];
            #pragma unroll
            for (int bi = 0; bi < 2; bi++) {
                uint32_t r[4];
                ldsm4(r, bBase + ((wn + bi * 16 + (lane >> 4) * 8 + (lane & 7)) * MSTR
                                  + kk * 16 + (lane & 8)) * 2);
                b[2 * bi][0] = r[0]; b[2 * bi][1] = r[1];
                b[2 * bi + 1][0] = r[2]; b[2 * bi + 1][1] = r[3];
            }
            #pragma unroll
            for (int mi = 0; mi < 2; mi++)
                #pragma unroll
                for (int ni = 0; ni < 4; ni++)
                    mma16816(acc[mi][ni], a[mi], b[ni]);
        }
        __syncthreads();
    }

    const int g = lane >> 2, tg = lane & 3;
    float v[2][2][4][2];
    #pragma unroll
    for (int mi = 0; mi < 2; mi++) {
        const int row = m0 + wm + mi * 16 + g;
        #pragma unroll
        for (int ni = 0; ni < 4; ni++) {
            const int col = wn + ni * 8 + tg * 2;
            const float b0 = bias[col], b1 = bias[col + 1];
            float2* p = (float2*)&H[(long long)row * DD + col];
            float2 h = *p;
            h.x += acc[mi][ni][0] + b0; h.y += acc[mi][ni][1] + b1;
            *p = h; v[mi][0][ni][0] = h.x; v[mi][0][ni][1] = h.y;
            p = (float2*)&H[(long long)(row + 8) * DD + col];
            h = *p;
            h.x += acc[mi][ni][2] + b0; h.y += acc[mi][ni][3] + b1;
            *p = h; v[mi][1][ni][0] = h.x; v[mi][1][ni][1] = h.y;
        }
    }
    #pragma unroll
    for (int mi = 0; mi < 2; mi++)
        #pragma unroll
        for (int rh = 0; rh < 2; rh++) {
            float s = 0.f;
            #pragma unroll
            for (int ni = 0; ni < 4; ni++) s += v[mi][rh][ni][0] + v[mi][rh][ni][1];
            s += __shfl_xor_sync(0xffffffffu, s, 1);
            s += __shfl_xor_sync(0xffffffffu, s, 2);
            if (tg == 0) rs[wm + mi * 16 + rh * 8 + g][nw] = s;
        }
    __syncthreads();
    float mu[2][2];
    #pragma unroll
    for (int mi = 0; mi < 2; mi++)
        #pragma unroll
        for (int rh = 0; rh < 2; rh++) {
            const int lr = wm + mi * 16 + rh * 8 + g;
            mu[mi][rh] = (rs[lr][0] + rs[lr][1] + rs[lr][2] + rs[lr][3]) * (1.f / DD);
        }
    __syncthreads();
    #pragma unroll
    for (int mi = 0; mi < 2; mi++)
        #pragma unroll
        for (int rh = 0; rh < 2; rh++) {
            float s = 0.f;
            #pragma unroll
            for (int ni = 0; ni < 4; ni++) {
                float d0 = v[mi][rh][ni][0] - mu[mi][rh];
                float d1 = v[mi][rh][ni][1] - mu[mi][rh];
                s += d0 * d0 + d1 * d1;
            }
            s += __shfl_xor_sync(0xffffffffu, s, 1);
            s += __shfl_xor_sync(0xffffffffu, s, 2);
            if (tg == 0) rs[wm + mi * 16 + rh * 8 + g][nw] = s;
        }
    __syncthreads();
    #pragma unroll
    for (int mi = 0; mi < 2; mi++) {
        #pragma unroll
        for (int rh = 0; rh < 2; rh++) {
            const int lr = wm + mi * 16 + rh * 8 + g;
            const float var = (rs[lr][0] + rs[lr][1] + rs[lr][2] + rs[lr][3]) * (1.f / DD);
            const float rsg = rsqrtf(var + 1e-5f);
            const long long row = m0 + lr;
            #pragma unroll
            for (int ni = 0; ni < 4; ni++) {
                const int col = wn + ni * 8 + tg * 2;
                *(__nv_bfloat162*)&g_H1b[row * DD + col] = __float22bfloat162_rn(make_float2(
                    (v[mi][rh][ni][0] - mu[mi][rh]) * rsg * lng[col] + lnb[col],
                    (v[mi][rh][ni][1] - mu[mi][rh]) * rsg * lng[col + 1] + lnb[col + 1]));
            }
        }
    }
}

// ---------------- flash (round-8 structure, exp2 softmax) + LN2 ----------------
// Q pre-scaled by log2(e)/sqrt(D); numerator = exp2(s) (no max; logits O(1)).
#define FSTR 136
#define QS_OFF   0
#define KS_OFF   17408
#define VS_OFF   (17408 + 2*34816)
#define FLASH_SMEM (17408 + 4*34816)   // 156672

__global__ void __launch_bounds__(128, 1)
flash_k(const __nv_bfloat16* __restrict__ Q, const __nv_bfloat16* __restrict__ K,
        const __nv_bfloat16* __restrict__ V, float* __restrict__ H,
        const float* __restrict__ lng, const float* __restrict__ lnb)
{
    extern __shared__ __align__(16) char fsm[];
    const int tid = threadIdx.x;
    const int lane = tid & 31;
    const int wid = tid >> 5;
    const int b = blockIdx.y;
    const int m0 = blockIdx.x * 64;
    const int wm = wid * 16;

    const uint32_t sQ = smem_u32(fsm) + QS_OFF;
    const uint32_t sK0 = smem_u32(fsm) + KS_OFF;
    const uint32_t sV0 = smem_u32(fsm) + VS_OFF;

    const __nv_bfloat16* Qg = Q + ((long long)b * TT + m0) * DD;
    const __nv_bfloat16* Kg = K + (long long)b * TT * DD;
    const __nv_bfloat16* Vg = V + (long long)b * TT * DD;

    const int lrow = tid >> 4;
    const int lch = (tid & 15) * 8;

    #pragma unroll
    for (int p = 0; p < 8; p++) {
        int row = lrow + p * 8;
        cp16(sQ + (row * FSTR + lch) * 2, Qg + (long long)row * DD + lch);
    }
    cp_commit();
    auto loadKV = [&](int c, int buf) {
        const __nv_bfloat16* kg = Kg + (long long)c * 128 * DD;
        uint32_t dk = sK0 + buf * 34816;
        #pragma unroll
        for (int p = 0; p < 16; p++) {
            int row = lrow + p * 8;
            cp16(dk + (row * FSTR + lch) * 2, kg + (long long)row * DD + lch);
        }
        const __nv_bfloat16* vg = Vg + (long long)c * 128 * DD;
        uint32_t dv = sV0 + buf * 34816;
        #pragma unroll
        for (int p = 0; p < 16; p++) {
            int row = lrow + p * 8;
            cp16(dv + (row * FSTR + lch) * 2, vg + (long long)row * DD + lch);
        }
        cp_commit();
    };

    loadKV(0, 0);
    cp_wait1();          // Q group retired
    __syncthreads();

    // hoist Q fragments for the whole KV loop
    uint32_t aq[8][4];
    #pragma unroll
    for (int kk = 0; kk < 8; kk++)
        ldsm4(aq[kk], sQ + ((wm + (lane & 15)) * FSTR + kk * 16 + (lane >> 4) * 8) * 2);

    float oa[16][4];
    #pragma unroll
    for (int j = 0; j < 16; j++)
        #pragma unroll
        for (int q = 0; q < 4; q++) oa[j][q] = 0.f;
    float l0 = 0.f, l1 = 0.f;

    const int NKV = TT / 128;
    for (int c = 0; c < NKV; c++) {
        const int buf = c & 1;
        if (c + 1 < NKV) { loadKV(c + 1, buf ^ 1); cp_wait1(); }
        else            { cp_wait0(); }
        __syncthreads();

        const uint32_t kB = sK0 + buf * 34816;
        const uint32_t vB = sV0 + buf * 34816;

        float sa[16][4];
        #pragma unroll
        for (int j = 0; j < 16; j++)
            #pragma unroll
            for (int q = 0; q < 4; q++) sa[j][q] = 0.f;

        #pragma unroll
        for (int kk = 0; kk < 8; kk++) {
            #pragma unroll
            for (int bi = 0; bi < 8; bi++) {
                uint32_t r[4];
                ldsm4(r, kB + ((bi * 16 + (lane >> 4) * 8 + (lane & 7)) * FSTR
                               + kk * 16 + (lane & 8)) * 2);
                uint32_t b0[2] = { r[0], r[1] }, b1[2] = { r[2], r[3] };
                mma16816(sa[2 * bi], aq[kk], b0);
                mma16816(sa[2 * bi + 1], aq[kk], b1);
            }
        }

        // ---- p = exp2(s) (Q carries log2e), accumulate l per-thread ----
        uint32_t pa[8][4];
        #pragma unroll
        for (int kk = 0; kk < 8; kk++) {
            float p00 = exp2f(sa[2*kk][0]),   p01 = exp2f(sa[2*kk][1]);
            float p02 = exp2f(sa[2*kk][2]),   p03 = exp2f(sa[2*kk][3]);
            float p10 = exp2f(sa[2*kk+1][0]), p11 = exp2f(sa[2*kk+1][1]);
            float p12 = exp2f(sa[2*kk+1][2]), p13 = exp2f(sa[2*kk+1][3]);
            l0 += p00 + p01 + p10 + p11;
            l1 += p02 + p03 + p12 + p13;
            __nv_bfloat162 h;
            h = __float22bfloat162_rn(make_float2(p00, p01)); pa[kk][0] = *(uint32_t*)&h;
            h = __float22bfloat162_rn(make_float2(p02, p03)); pa[kk][1] = *(uint32_t*)&h;
            h = __float22bfloat162_rn(make_float2(p10, p11)); pa[kk][2] = *(uint32_t*)&h;
            h = __float22bfloat162_rn(make_float2(p12, p13)); pa[kk][3] = *(uint32_t*)&h;
        }

        #pragma unroll
        for (int kk = 0; kk < 8; kk++) {
            #pragma unroll
            for (int bi = 0; bi < 8; bi++) {
                uint32_t r[4];
                ldsm4t(r, vB + ((kk * 16 + (lane & 15)) * FSTR
                                + bi * 16 + (lane >> 4) * 8) * 2);
                uint32_t b0[2] = { r[0], r[1] }, b1[2] = { r[2], r[3] };
                mma16816(oa[2 * bi], pa[kk], b0);
                mma16816(oa[2 * bi + 1], pa[kk], b1);
            }
        }
        __syncthreads();
    }

    // single end-of-loop row-sum reduce
    l0 += __shfl_xor_sync(0xffffffffu, l0, 1);
    l0 += __shfl_xor_sync(0xffffffffu, l0, 2);
    l1 += __shfl_xor_sync(0xffffffffu, l1, 1);
    l1 += __shfl_xor_sync(0xffffffffu, l1, 2);

    // ---- epilogue: H += O/l, then LN2 -> H1b ----
    const float inv0 = 1.f / l0, inv1 = 1.f / l1;
    const int g = lane >> 2, tg = lane & 3;
    const long long row0 = (long long)b * TT + m0 + wm + g;
    float s0 = 0.f, s1 = 0.f;
    #pragma unroll
    for (int j = 0; j < 16; j++) {
        const int col = j * 8 + tg * 2;
        float2* p = (float2*)&H[row0 * DD + col];
        float2 v = *p;
        v.x += oa[j][0] * inv0; v.y += oa[j][1] * inv0;
        *p = v; oa[j][0] = v.x; oa[j][1] = v.y;
        s0 += v.x + v.y;
        p = (float2*)&H[(row0 + 8) * DD + col];
        v = *p;
        v.x += oa[j][2] * inv1; v.y += oa[j][3] * inv1;
        *p = v; oa[j][2] = v.x; oa[j][3] = v.y;
        s1 += v.x + v.y;
    }
    s0 += __shfl_xor_sync(0xffffffffu, s0, 1);
    s0 += __shfl_xor_sync(0xffffffffu, s0, 2);
    s1 += __shfl_xor_sync(0xffffffffu, s1, 1);
    s1 += __shfl_xor_sync(0xffffffffu, s1, 2);
    const float mu0 = s0 * (1.f / DD), mu1 = s1 * (1.f / DD);
    float q0 = 0.f, q1 = 0.f;
    #pragma unroll
    for (int j = 0; j < 16; j++) {
        float d0 = oa[j][0] - mu0, d1 = oa[j][1] - mu0;
        q0 += d0 * d0 + d1 * d1;
        float d2 = oa[j][2] - mu1, d3 = oa[j][3] - mu1;
        q1 += d2 * d2 + d3 * d3;
    }
    q0 += __shfl_xor_sync(0xffffffffu, q0, 1);
    q0 += __shfl_xor_sync(0xffffffffu, q0, 2);
    q1 += __shfl_xor_sync(0xffffffffu, q1, 1);
    q1 += __shfl_xor_sync(0xffffffffu, q1, 2);
    const float rs0 = rsqrtf(q0 * (1.f / DD) + 1e-5f);
    const float rs1 = rsqrtf(q1 * (1.f / DD) + 1e-5f);
    #pragma unroll
    for (int j = 0; j < 16; j++) {
        const int col = j * 8 + tg * 2;
        const float ga = lng[col], gb2 = lng[col + 1];
        const float ba = lnb[col], bb2 = lnb[col + 1];
        *(__nv_bfloat162*)&g_H1b[row0 * DD + col] = __float22bfloat162_rn(make_float2(
            (oa[j][0] - mu0) * rs0 * ga + ba, (oa[j][1] - mu0) * rs0 * gb2 + bb2));
        *(__nv_bfloat162*)&g_H1b[(row0 + 8) * DD + col] = __float22bfloat162_rn(make_float2(
            (oa[j][2] - mu1) * rs1 * ga + ba, (oa[j][3] - mu1) * rs1 * gb2 + bb2));
    }
}

// ---------------- readout ----------------
__global__ void readout_k(const float* __restrict__ Wro, const float* __restrict__ bro,
                          float* __restrict__ out)
{
    int r = blockIdx.x * 8 + (threadIdx.x >> 5);
    int lane = threadIdx.x & 31;
    float4 h = *(const float4*)&g_H[r * DD + lane * 4];
    float4 w = *(const float4*)&Wro[lane * 4];
    float s = h.x * w.x + h.y * w.y + h.z * w.z + h.w * w.w;
    #pragma unroll
    for (int o = 16; o; o >>= 1) s += __shfl_xor_sync(0xffffffffu, s, o);
    if (lane == 0) out[r] = s + bro[0];
}

// ---------------- host launcher ----------------
extern "C" void kernel_launch(void* const* d_in, const int* in_sizes, int n_in,
                              void* d_out, int out_size)
{
    (void)in_sizes; (void)n_in; (void)out_size;
    const int*   x    = (const int*)  d_in[0];
    const float* pos  = (const float*)d_in[1];
    const float* Wq   = (const float*)d_in[2];
    const float* Wk   = (const float*)d_in[3];
    const float* Wv   = (const float*)d_in[4];
    const float* ln1g = (const float*)d_in[5];
    const float* ln1b = (const float*)d_in[6];
    const float* W1   = (const float*)d_in[7];
    const float* b1   = (const float*)d_in[8];
    const float* W2   = (const float*)d_in[9];
    const float* b2   = (const float*)d_in[10];
    const float* ln2g = (const float*)d_in[11];
    const float* ln2b = (const float*)d_in[12];
    const float* Wro  = (const float*)d_in[13];
    const float* bro  = (const float*)d_in[14];
    float* out = (float*)d_out;

    float *pH; __nv_bfloat16 *pH1b, *pQb, *pKb, *pVb, *pM1b;
    __nv_bfloat16 *pWqkvb, *pW1b, *pW2b;
    cudaGetSymbolAddress((void**)&pH,    g_H);
    cudaGetSymbolAddress((void**)&pH1b,  g_H1b);
    cudaGetSymbolAddress((void**)&pQb,   g_Qb);
    cudaGetSymbolAddress((void**)&pKb,   g_Kb);
    cudaGetSymbolAddress((void**)&pVb,   g_Vb);
    cudaGetSymbolAddress((void**)&pM1b,  g_M1b);
    cudaGetSymbolAddress((void**)&pWqkvb, g_Wqkvb);
    cudaGetSymbolAddress((void**)&pW1b,  g_W1b);
    cudaGetSymbolAddress((void**)&pW2b,  g_W2b);

    const int GS_SMEM = 2 * 128 * GSTR * 2;   // 69632
    cudaFuncSetAttribute(flash_k, cudaFuncAttributeMaxDynamicSharedMemorySize, FLASH_SMEM);
    cudaFuncSetAttribute(gemm_ks<6>, cudaFuncAttributeMaxDynamicSharedMemorySize, GS_SMEM);
    cudaFuncSetAttribute(gemm_ks<3>, cudaFuncAttributeMaxDynamicSharedMemorySize, GS_SMEM);

    // Q pre-scale folds 1/sqrt(D) and log2(e) so flash uses bare exp2
    const float q_scale = (1.f / sqrtf((float)DD)) * 1.4426950408889634f;

    convall_k<<<(NQKV + NW1 + NW2 + 255) / 256, 256>>>(Wq, Wk, Wv, W1, W2);
    embed_ln_k<<<BTT, 128>>>(x, pos, ln1g, ln1b);

    for (int l = 0; l < LL; l++) {
        {
            dim3 g(BTT/128, 3, 1);
            gemm_ks<6><<<g, 256, GS_SMEM>>>(pH1b, pWqkvb + (size_t)l*3*DD*DD, nullptr,
                                            nullptr, DD, q_scale);
        }
        {
            dim3 g(TT/64, BB);
            flash_k<<<g, 128, FLASH_SMEM>>>(pQb, pKb, pVb, pH, ln2g + l*DD, ln2b + l*DD);
        }
        {
            dim3 g(BTT/128, HMM/128, 1);
            gemm_ks<3><<<g, 256, GS_SMEM>>>(pH1b, pW1b + (size_t)l*HMM*DD, b1 + (size_t)l*HMM,
                                            pM1b, HMM, 1.f);
        }
        {
            const int ln = (l + 1) % LL;
            mlp2_k<<<BTT/64, 256>>>(pM1b, pW2b + (size_t)l*DD*HMM, b2 + (size_t)l*DD,
                                    pH, ln1g + (size_t)ln*DD, ln1b + (size_t)ln*DD);
        }
    }

    readout_k<<<BTT / 8, 256>>>(Wro, bro, out);
}